// round 15
// baseline (speedup 1.0000x reference)
#include <cuda_runtime.h>
#include <cuda_bf16.h>

#define NE    32
#define NNUC  8
#define NCHI  8
#define NU    8
#define WPB   8      // walkers per block (2 warps each -> 512 threads)

typedef unsigned long long u64;

// ---- f32x2 packed helpers (Blackwell) ----
__device__ __forceinline__ u64 pk2(float lo, float hi) {
    u64 r; asm("mov.b64 %0, {%1, %2};" : "=l"(r) : "f"(lo), "f"(hi)); return r;
}
__device__ __forceinline__ void upk2(u64 v, float& lo, float& hi) {
    asm("mov.b64 {%0, %1}, %2;" : "=f"(lo), "=f"(hi) : "l"(v));
}
__device__ __forceinline__ u64 fma2(u64 a, u64 b, u64 c) {
    u64 d; asm("fma.rn.f32x2 %0, %1, %2, %3;" : "=l"(d) : "l"(a), "l"(b), "l"(c)); return d;
}
__device__ __forceinline__ u64 mul2(u64 a, u64 b) {
    u64 d; asm("mul.rn.f32x2 %0, %1, %2;" : "=l"(d) : "l"(a), "l"(b)); return d;
}

// Flat float4-chunk indices (i*8 + c) of the 136 chunks touching the strict
// upper triangle of the 32x32 elec matrix. Staged through SHARED (broadcast-
// friendly LDS) — NOT __constant__: divergent per-lane constant indexing
// serializes on the broadcast-only constant port (R8/R12 regressions).
static __device__ const unsigned char UPPER_TAB[136] = {
    0,1,2,3,4,5,6,7,
    8,9,10,11,12,13,14,15,
    16,17,18,19,20,21,22,23,
    25,26,27,28,29,30,31,
    33,34,35,36,37,38,39,
    41,42,43,44,45,46,47,
    49,50,51,52,53,54,55,
    58,59,60,61,62,63,
    66,67,68,69,70,71,
    74,75,76,77,78,79,
    82,83,84,85,86,87,
    91,92,93,94,95,
    99,100,101,102,103,
    107,108,109,110,111,
    115,116,117,118,119,
    124,125,126,127,
    132,133,134,135,
    140,141,142,143,
    148,149,150,151,
    157,158,159,
    165,166,167,
    173,174,175,
    181,182,183,
    190,191,
    198,199,
    206,207,
    214,215,
    223,
    231,
    239,
    247
};

__global__ __launch_bounds__(512, 2)
void jastrow_kernel(
    const float4* __restrict__ elec4,   // [B, 256]
    const float4* __restrict__ nuc4,    // [B, 64]
    const float* __restrict__ alpha,    // [8]
    const float* __restrict__ beta,     // [3, 8]
    const float* __restrict__ Zarr,     // [8]
    const float* __restrict__ Lchi,     // [3]
    const float* __restrict__ Lu_p,     // [1]
    const int*   __restrict__ type_idx, // [8]
    float* __restrict__ out)            // [B]
{
    __shared__ u64 s_ss2, s_sd2;        // slope same/diff packed
    __shared__ u64 s_hi2[4][NCHI - 1];  // beta[1..7]/8 for nucleus pair (2p,2p+1)
    __shared__ u64 s_c02[4];            // beta0/8 pair-packed
    __shared__ u64 s_lin2[4];           // lin/8 pair-packed
    __shared__ float s_L[NNUC];
    __shared__ float s_Lu;
    __shared__ int  s_info[136];        // chunk | mask<<8 | same<<12
    __shared__ float s_part[16];

    const int t    = threadIdx.x;
    const int lane = t & 31;
    const int warp = t >> 5;            // 0..15
    const int wk   = warp >> 1;         // walker in block 0..7
    const int b    = blockIdx.x * WPB + wk;
    const int l    = (warp & 1) * 32 + lane;   // 0..63 within walker team

    // ---- setup ----
    if (t < NNUC) s_L[t] = Lchi[type_idx[t]];
    if (t == 16) {
        float Lu = Lu_p[0];
        s_Lu = Lu;
        float a0 = alpha[0];
        float negL3 = -(Lu * Lu * Lu);
        float ss = 0.25f / negL3 + a0 * 3.0f / Lu;
        float sd = 0.50f / negL3 + a0 * 3.0f / Lu;
        s_ss2 = pk2(ss, ss);
        s_sd2 = pk2(sd, sd);
    }
    if (t >= 32 && t < 32 + 28) {       // pack beta high coefs per nucleus pair
        int k = t - 32, pr = k / 7, q = k % 7;
        int m0 = 2 * pr, m1 = m0 + 1;
        int ty0 = type_idx[m0], ty1 = type_idx[m1];
        s_hi2[pr][q] = pk2(beta[ty0 * NCHI + q + 1] * 0.125f,
                           beta[ty1 * NCHI + q + 1] * 0.125f);
    }
    if (t >= 64 && t < 68) {            // c0 and lin pair-packed
        int pr = t - 64;
        int m0 = 2 * pr, m1 = m0 + 1;
        int ty0 = type_idx[m0], ty1 = type_idx[m1];
        float L0 = Lchi[ty0], L1 = Lchi[ty1];
        float b00 = beta[ty0 * NCHI], b01 = beta[ty1 * NCHI];
        float lin0 = (-Zarr[m0] / (-(L0 * L0 * L0)) + b00 * 3.0f / L0) * 0.125f;
        float lin1 = (-Zarr[m1] / (-(L1 * L1 * L1)) + b01 * 3.0f / L1) * 0.125f;
        s_c02[pr]  = pk2(b00 * 0.125f, b01 * 0.125f);
        s_lin2[pr] = pk2(lin0, lin1);
    }
    if (t >= 120 && t < 120 + 136) {    // info table (global const -> shared)
        int k = t - 120;
        int v = UPPER_TAB[k];
        int i = v >> 3, jb = (v & 7) * 4;
        int mask = 0;
        #pragma unroll
        for (int p = 0; p < 4; ++p) if (jb + p > i) mask |= 1 << p;
        int same = ((i < 16) == (jb < 16)) ? 1 : 0;
        s_info[k] = v | (mask << 8) | (same << 12);
    }

    // ---- alpha coefficients straight into registers (no smem in hot path) ----
    u64 a2[NU];
    #pragma unroll
    for (int q = 0; q < NU; ++q) { float a = alpha[q]; a2[q] = pk2(a, a); }

    __syncthreads();

    // ---- issue all data loads in one burst ----
    float4 rn = __ldg(nuc4 + (size_t)b * 64 + l);

    const float4* erow = elec4 + (size_t)b * 256;
    int info0 = s_info[l];
    int info1 = s_info[l + 64];
    float4 e0 = __ldg(erow + (info0 & 255));
    float4 e1 = __ldg(erow + (info1 & 255));
    float4 e2;
    int info2 = 0;
    const bool has2 = (l < 8);
    if (has2) { info2 = s_info[128 + l]; e2 = __ldg(erow + (info2 & 255)); }

    const u64 ss2 = s_ss2, sd2 = s_sd2;

    u64 acc2 = pk2(0.f, 0.f);

    // ---- e-N chunk: nuclei mb..mb+3, coef pairs pr0, pr0+1 (smem coefs) ----
    {
        const int pr0 = (l & 1) * 2;
        const int mb  = (l & 1) * 4;
        float d0 = fminf(rn.x - s_L[mb + 0], 0.f);
        float d1 = fminf(rn.y - s_L[mb + 1], 0.f);
        float d2 = fminf(rn.z - s_L[mb + 2], 0.f);
        float d3 = fminf(rn.w - s_L[mb + 3], 0.f);
        u64 rA = pk2(rn.x, rn.y), rB = pk2(rn.z, rn.w);
        u64 dA = pk2(d0, d1),     dB = pk2(d2, d3);
        u64 envA = mul2(mul2(dA, dA), dA);
        u64 envB = mul2(mul2(dB, dB), dB);
        u64 pA = s_hi2[pr0][6];
        u64 pB = s_hi2[pr0 + 1][6];
        #pragma unroll
        for (int q = 5; q >= 0; --q) {
            pA = fma2(pA, rA, s_hi2[pr0][q]);
            pB = fma2(pB, rB, s_hi2[pr0 + 1][q]);
        }
        u64 rA2 = mul2(rA, rA), rB2 = mul2(rB, rB);
        pA = fma2(pA, rA2, fma2(s_lin2[pr0],     rA, s_c02[pr0]));
        pB = fma2(pB, rB2, fma2(s_lin2[pr0 + 1], rB, s_c02[pr0 + 1]));
        acc2 = fma2(envA, pA, acc2);
        acc2 = fma2(envB, pB, acc2);
    }

    // ---- e-e chunks: pure-register Horner ----
    const float Lu = s_Lu;

    auto do_chunk = [&](int info, const float4& v) {
        int mask = (info >> 8) & 15;
        u64 slope2 = (info & 0x1000) ? ss2 : sd2;
        float d0 = (mask & 1) ? fminf(v.x - Lu, 0.f) : 0.f;
        float d1 = (mask & 2) ? fminf(v.y - Lu, 0.f) : 0.f;
        float d2 = (mask & 4) ? fminf(v.z - Lu, 0.f) : 0.f;
        float d3 = (mask & 8) ? fminf(v.w - Lu, 0.f) : 0.f;
        u64 rA = pk2(v.x, v.y), rB = pk2(v.z, v.w);
        u64 dA = pk2(d0, d1),   dB = pk2(d2, d3);
        u64 envA = mul2(mul2(dA, dA), dA);
        u64 envB = mul2(mul2(dB, dB), dB);
        u64 pA = a2[NU - 1];
        u64 pB = a2[NU - 1];
        #pragma unroll
        for (int q = NU - 2; q >= 1; --q) {
            pA = fma2(pA, rA, a2[q]);
            pB = fma2(pB, rB, a2[q]);
        }
        u64 rA2 = mul2(rA, rA), rB2 = mul2(rB, rB);
        pA = fma2(pA, rA2, fma2(slope2, rA, a2[0]));
        pB = fma2(pB, rB2, fma2(slope2, rB, a2[0]));
        acc2 = fma2(envA, pA, acc2);
        acc2 = fma2(envB, pB, acc2);
    };

    do_chunk(info0, e0);
    do_chunk(info1, e1);
    if (has2) do_chunk(info2, e2);

    // ---- reduce ----
    float aLo, aHi;
    upk2(acc2, aLo, aHi);
    float acc = aLo + aHi;
    #pragma unroll
    for (int off = 16; off > 0; off >>= 1)
        acc += __shfl_down_sync(0xffffffffu, acc, off);
    if (lane == 0) s_part[warp] = acc;
    __syncthreads();
    if (t < WPB)
        out[blockIdx.x * WPB + t] = s_part[2 * t] + s_part[2 * t + 1];
}

extern "C" void kernel_launch(void* const* d_in, const int* in_sizes, int n_in,
                              void* d_out, int out_size)
{
    const float4* elec  = (const float4*)d_in[0];
    const float4* nuc   = (const float4*)d_in[1];
    const float* alpha  = (const float*)d_in[2];
    const float* beta   = (const float*)d_in[3];
    const float* Z      = (const float*)d_in[4];
    const float* Lchi   = (const float*)d_in[5];
    const float* Lu     = (const float*)d_in[6];
    const int*   tidx   = (const int*)  d_in[7];
    float* out = (float*)d_out;

    int B = in_sizes[1] / (NE * NNUC);   // 4096

    jastrow_kernel<<<B / WPB, 512>>>(elec, nuc, alpha, beta, Z, Lchi, Lu, tidx, out);
}

// round 16
// speedup vs baseline: 1.1343x; 1.1343x over previous
#include <cuda_runtime.h>
#include <cuda_bf16.h>

#define NE    32
#define NNUC  8
#define NCHI  8
#define NU    8
#define WPB   16     // walkers per block: 8 teams x 2 passes (512 threads)

typedef unsigned long long u64;

// ---- f32x2 packed helpers (Blackwell) ----
__device__ __forceinline__ u64 pk2(float lo, float hi) {
    u64 r; asm("mov.b64 %0, {%1, %2};" : "=l"(r) : "f"(lo), "f"(hi)); return r;
}
__device__ __forceinline__ void upk2(u64 v, float& lo, float& hi) {
    asm("mov.b64 {%0, %1}, %2;" : "=f"(lo), "=f"(hi) : "l"(v));
}
__device__ __forceinline__ u64 fma2(u64 a, u64 b, u64 c) {
    u64 d; asm("fma.rn.f32x2 %0, %1, %2, %3;" : "=l"(d) : "l"(a), "l"(b), "l"(c)); return d;
}
__device__ __forceinline__ u64 mul2(u64 a, u64 b) {
    u64 d; asm("mul.rn.f32x2 %0, %1, %2;" : "=l"(d) : "l"(a), "l"(b)); return d;
}

// Flat float4-chunk indices (i*8 + c) of the 136 chunks touching the strict
// upper triangle of the 32x32 elec matrix. Staged through SHARED (broadcast-
// friendly LDS) — NOT __constant__ (divergent constant indexing serializes).
static __device__ const unsigned char UPPER_TAB[136] = {
    0,1,2,3,4,5,6,7,
    8,9,10,11,12,13,14,15,
    16,17,18,19,20,21,22,23,
    25,26,27,28,29,30,31,
    33,34,35,36,37,38,39,
    41,42,43,44,45,46,47,
    49,50,51,52,53,54,55,
    58,59,60,61,62,63,
    66,67,68,69,70,71,
    74,75,76,77,78,79,
    82,83,84,85,86,87,
    91,92,93,94,95,
    99,100,101,102,103,
    107,108,109,110,111,
    115,116,117,118,119,
    124,125,126,127,
    132,133,134,135,
    140,141,142,143,
    148,149,150,151,
    157,158,159,
    165,166,167,
    173,174,175,
    181,182,183,
    190,191,
    198,199,
    206,207,
    214,215,
    223,
    231,
    239,
    247
};

__global__ __launch_bounds__(512, 2)
void jastrow_kernel(
    const float4* __restrict__ elec4,   // [B, 256]
    const float4* __restrict__ nuc4,    // [B, 64]
    const float* __restrict__ alpha,    // [8]
    const float* __restrict__ beta,     // [3, 8]
    const float* __restrict__ Zarr,     // [8]
    const float* __restrict__ Lchi,     // [3]
    const float* __restrict__ Lu_p,     // [1]
    const int*   __restrict__ type_idx, // [8]
    float* __restrict__ out)            // [B]
{
    __shared__ u64 s_ss2, s_sd2;        // slope same/diff packed
    __shared__ u64 s_hi2[4][NCHI - 1];  // beta[1..7]/8 for nucleus pair (2p,2p+1)
    __shared__ u64 s_c02[4];            // beta0/8 pair-packed
    __shared__ u64 s_lin2[4];           // lin/8 pair-packed
    __shared__ float s_L[NNUC];
    __shared__ float s_Lu;
    __shared__ int  s_info[136];        // chunk | mask<<8 | same<<12
    __shared__ float s_part[2][16];     // per-pass partials (double-buffered)

    const int t    = threadIdx.x;
    const int lane = t & 31;
    const int warp = t >> 5;            // 0..15
    const int wk   = warp >> 1;         // team (walker slot) in block 0..7
    const int l    = (warp & 1) * 32 + lane;   // 0..63 within team

    // ---- one-time setup (amortized over 16 walkers) ----
    if (t < NNUC) s_L[t] = Lchi[type_idx[t]];
    if (t == 16) {
        float Lu = Lu_p[0];
        s_Lu = Lu;
        float a0 = alpha[0];
        float negL3 = -(Lu * Lu * Lu);
        float ss = 0.25f / negL3 + a0 * 3.0f / Lu;
        float sd = 0.50f / negL3 + a0 * 3.0f / Lu;
        s_ss2 = pk2(ss, ss);
        s_sd2 = pk2(sd, sd);
    }
    if (t >= 32 && t < 32 + 28) {       // pack beta high coefs per nucleus pair
        int k = t - 32, pr = k / 7, q = k % 7;
        int m0 = 2 * pr, m1 = m0 + 1;
        int ty0 = type_idx[m0], ty1 = type_idx[m1];
        s_hi2[pr][q] = pk2(beta[ty0 * NCHI + q + 1] * 0.125f,
                           beta[ty1 * NCHI + q + 1] * 0.125f);
    }
    if (t >= 64 && t < 68) {            // c0 and lin pair-packed
        int pr = t - 64;
        int m0 = 2 * pr, m1 = m0 + 1;
        int ty0 = type_idx[m0], ty1 = type_idx[m1];
        float L0 = Lchi[ty0], L1 = Lchi[ty1];
        float b00 = beta[ty0 * NCHI], b01 = beta[ty1 * NCHI];
        float lin0 = (-Zarr[m0] / (-(L0 * L0 * L0)) + b00 * 3.0f / L0) * 0.125f;
        float lin1 = (-Zarr[m1] / (-(L1 * L1 * L1)) + b01 * 3.0f / L1) * 0.125f;
        s_c02[pr]  = pk2(b00 * 0.125f, b01 * 0.125f);
        s_lin2[pr] = pk2(lin0, lin1);
    }
    if (t >= 120 && t < 120 + 136) {    // info table (global const -> shared)
        int k = t - 120;
        int v = UPPER_TAB[k];
        int i = v >> 3, jb = (v & 7) * 4;
        int mask = 0;
        #pragma unroll
        for (int p = 0; p < 4; ++p) if (jb + p > i) mask |= 1 << p;
        int same = ((i < 16) == (jb < 16)) ? 1 : 0;
        s_info[k] = v | (mask << 8) | (same << 12);
    }

    // ---- alpha coefficients straight into registers ----
    u64 a2[NU];
    #pragma unroll
    for (int q = 0; q < NU; ++q) { float a = alpha[q]; a2[q] = pk2(a, a); }

    __syncthreads();

    // per-team invariants (fixed across passes)
    const int info0 = s_info[l];
    const int info1 = s_info[l + 64];
    const bool has2 = (l < 8);
    const int info2 = has2 ? s_info[128 + l] : 0;
    const u64 ss2 = s_ss2, sd2 = s_sd2;
    const float Lu = s_Lu;
    const int pr0 = (l & 1) * 2;
    const int mb  = (l & 1) * 4;
    const float Ln0 = s_L[mb], Ln1 = s_L[mb + 1], Ln2 = s_L[mb + 2], Ln3 = s_L[mb + 3];

    // ==================== 2 passes x 8 walkers ====================
    #pragma unroll
    for (int pass = 0; pass < 2; ++pass) {
        const int b = blockIdx.x * WPB + pass * 8 + wk;

        // ---- loads for this pass ----
        float4 rn = __ldg(nuc4 + (size_t)b * 64 + l);
        const float4* erow = elec4 + (size_t)b * 256;
        float4 e0 = __ldg(erow + (info0 & 255));
        float4 e1 = __ldg(erow + (info1 & 255));
        float4 e2;
        if (has2) e2 = __ldg(erow + (info2 & 255));

        u64 acc2 = pk2(0.f, 0.f);

        // ---- e-N chunk ----
        {
            float d0 = fminf(rn.x - Ln0, 0.f);
            float d1 = fminf(rn.y - Ln1, 0.f);
            float d2 = fminf(rn.z - Ln2, 0.f);
            float d3 = fminf(rn.w - Ln3, 0.f);
            u64 rA = pk2(rn.x, rn.y), rB = pk2(rn.z, rn.w);
            u64 dA = pk2(d0, d1),     dB = pk2(d2, d3);
            u64 envA = mul2(mul2(dA, dA), dA);
            u64 envB = mul2(mul2(dB, dB), dB);
            u64 pA = s_hi2[pr0][6];
            u64 pB = s_hi2[pr0 + 1][6];
            #pragma unroll
            for (int q = 5; q >= 0; --q) {
                pA = fma2(pA, rA, s_hi2[pr0][q]);
                pB = fma2(pB, rB, s_hi2[pr0 + 1][q]);
            }
            u64 rA2 = mul2(rA, rA), rB2 = mul2(rB, rB);
            pA = fma2(pA, rA2, fma2(s_lin2[pr0],     rA, s_c02[pr0]));
            pB = fma2(pB, rB2, fma2(s_lin2[pr0 + 1], rB, s_c02[pr0 + 1]));
            acc2 = fma2(envA, pA, acc2);
            acc2 = fma2(envB, pB, acc2);
        }

        // ---- e-e chunks: pure-register Horner ----
        auto do_chunk = [&](int info, const float4& v) {
            int mask = (info >> 8) & 15;
            u64 slope2 = (info & 0x1000) ? ss2 : sd2;
            float d0 = (mask & 1) ? fminf(v.x - Lu, 0.f) : 0.f;
            float d1 = (mask & 2) ? fminf(v.y - Lu, 0.f) : 0.f;
            float d2 = (mask & 4) ? fminf(v.z - Lu, 0.f) : 0.f;
            float d3 = (mask & 8) ? fminf(v.w - Lu, 0.f) : 0.f;
            u64 rA = pk2(v.x, v.y), rB = pk2(v.z, v.w);
            u64 dA = pk2(d0, d1),   dB = pk2(d2, d3);
            u64 envA = mul2(mul2(dA, dA), dA);
            u64 envB = mul2(mul2(dB, dB), dB);
            u64 pA = a2[NU - 1];
            u64 pB = a2[NU - 1];
            #pragma unroll
            for (int q = NU - 2; q >= 1; --q) {
                pA = fma2(pA, rA, a2[q]);
                pB = fma2(pB, rB, a2[q]);
            }
            u64 rA2 = mul2(rA, rA), rB2 = mul2(rB, rB);
            pA = fma2(pA, rA2, fma2(slope2, rA, a2[0]));
            pB = fma2(pB, rB2, fma2(slope2, rB, a2[0]));
            acc2 = fma2(envA, pA, acc2);
            acc2 = fma2(envB, pB, acc2);
        };

        do_chunk(info0, e0);
        do_chunk(info1, e1);
        if (has2) do_chunk(info2, e2);

        // ---- team reduce into double-buffered partials ----
        float aLo, aHi;
        upk2(acc2, aLo, aHi);
        float acc = aLo + aHi;
        #pragma unroll
        for (int off = 16; off > 0; off >>= 1)
            acc += __shfl_down_sync(0xffffffffu, acc, off);
        if (lane == 0) s_part[pass][warp] = acc;
    }

    __syncthreads();
    if (t < WPB) {
        int p = t >> 3, w8 = t & 7;
        out[blockIdx.x * WPB + t] = s_part[p][2 * w8] + s_part[p][2 * w8 + 1];
    }
}

extern "C" void kernel_launch(void* const* d_in, const int* in_sizes, int n_in,
                              void* d_out, int out_size)
{
    const float4* elec  = (const float4*)d_in[0];
    const float4* nuc   = (const float4*)d_in[1];
    const float* alpha  = (const float*)d_in[2];
    const float* beta   = (const float*)d_in[3];
    const float* Z      = (const float*)d_in[4];
    const float* Lchi   = (const float*)d_in[5];
    const float* Lu     = (const float*)d_in[6];
    const int*   tidx   = (const int*)  d_in[7];
    float* out = (float*)d_out;

    int B = in_sizes[1] / (NE * NNUC);   // 4096

    jastrow_kernel<<<B / WPB, 512>>>(elec, nuc, alpha, beta, Z, Lchi, Lu, tidx, out);
}

// round 17
// speedup vs baseline: 1.1630x; 1.0254x over previous
#include <cuda_runtime.h>
#include <cuda_bf16.h>

#define NE    32
#define NNUC  8
#define NCHI  8
#define NU    8

typedef unsigned long long u64;

// ---- f32x2 packed helpers (Blackwell) ----
__device__ __forceinline__ u64 pk2(float lo, float hi) {
    u64 r; asm("mov.b64 %0, {%1, %2};" : "=l"(r) : "f"(lo), "f"(hi)); return r;
}
__device__ __forceinline__ void upk2(u64 v, float& lo, float& hi) {
    asm("mov.b64 {%0, %1}, %2;" : "=f"(lo), "=f"(hi) : "l"(v));
}
__device__ __forceinline__ u64 fma2(u64 a, u64 b, u64 c) {
    u64 d; asm("fma.rn.f32x2 %0, %1, %2, %3;" : "=l"(d) : "l"(a), "l"(b), "l"(c)); return d;
}
__device__ __forceinline__ u64 mul2(u64 a, u64 b) {
    u64 d; asm("mul.rn.f32x2 %0, %1, %2;" : "=l"(d) : "l"(a), "l"(b)); return d;
}

// Flat float4-chunk indices (i*8 + c) of the 136 chunks touching the strict
// upper triangle of the 32x32 elec matrix. Staged through SHARED (broadcast-
// friendly LDS) — NOT __constant__ (divergent constant indexing serializes).
static __device__ const unsigned char UPPER_TAB[136] = {
    0,1,2,3,4,5,6,7,
    8,9,10,11,12,13,14,15,
    16,17,18,19,20,21,22,23,
    25,26,27,28,29,30,31,
    33,34,35,36,37,38,39,
    41,42,43,44,45,46,47,
    49,50,51,52,53,54,55,
    58,59,60,61,62,63,
    66,67,68,69,70,71,
    74,75,76,77,78,79,
    82,83,84,85,86,87,
    91,92,93,94,95,
    99,100,101,102,103,
    107,108,109,110,111,
    115,116,117,118,119,
    124,125,126,127,
    132,133,134,135,
    140,141,142,143,
    148,149,150,151,
    157,158,159,
    165,166,167,
    173,174,175,
    181,182,183,
    190,191,
    198,199,
    206,207,
    214,215,
    223,
    231,
    239,
    247
};

__global__ __launch_bounds__(512, 2)
void jastrow_kernel(
    const float4* __restrict__ elec4,   // [B, 256]
    const float4* __restrict__ nuc4,    // [B, 64]
    const float* __restrict__ alpha,    // [8]
    const float* __restrict__ beta,     // [3, 8]
    const float* __restrict__ Zarr,     // [8]
    const float* __restrict__ Lchi,     // [3]
    const float* __restrict__ Lu_p,     // [1]
    const int*   __restrict__ type_idx, // [8]
    float* __restrict__ out,            // [B]
    int B)
{
    __shared__ u64 s_ss2, s_sd2;        // slope same/diff packed
    __shared__ u64 s_hi2[4][NCHI - 1];  // beta[1..7]/8 for nucleus pair (2p,2p+1)
    __shared__ u64 s_c02[4];            // beta0/8 pair-packed
    __shared__ u64 s_lin2[4];           // lin/8 pair-packed
    __shared__ float s_L[NNUC];
    __shared__ float s_Lu;
    __shared__ int  s_info[136];        // chunk | mask<<8 | same<<12

    const int t    = threadIdx.x;
    const int lane = t & 31;
    const int warp = t >> 5;            // 0..15

    // ---- one-time block setup (amortized over ~14 walkers) ----
    if (t < NNUC) s_L[t] = Lchi[type_idx[t]];
    if (t == 16) {
        float Lu = Lu_p[0];
        s_Lu = Lu;
        float a0 = alpha[0];
        float negL3 = -(Lu * Lu * Lu);
        float ss = 0.25f / negL3 + a0 * 3.0f / Lu;
        float sd = 0.50f / negL3 + a0 * 3.0f / Lu;
        s_ss2 = pk2(ss, ss);
        s_sd2 = pk2(sd, sd);
    }
    if (t >= 32 && t < 32 + 28) {       // pack beta high coefs per nucleus pair
        int k = t - 32, pr = k / 7, q = k % 7;
        int m0 = 2 * pr, m1 = m0 + 1;
        int ty0 = type_idx[m0], ty1 = type_idx[m1];
        s_hi2[pr][q] = pk2(beta[ty0 * NCHI + q + 1] * 0.125f,
                           beta[ty1 * NCHI + q + 1] * 0.125f);
    }
    if (t >= 64 && t < 68) {            // c0 and lin pair-packed
        int pr = t - 64;
        int m0 = 2 * pr, m1 = m0 + 1;
        int ty0 = type_idx[m0], ty1 = type_idx[m1];
        float L0 = Lchi[ty0], L1 = Lchi[ty1];
        float b00 = beta[ty0 * NCHI], b01 = beta[ty1 * NCHI];
        float lin0 = (-Zarr[m0] / (-(L0 * L0 * L0)) + b00 * 3.0f / L0) * 0.125f;
        float lin1 = (-Zarr[m1] / (-(L1 * L1 * L1)) + b01 * 3.0f / L1) * 0.125f;
        s_c02[pr]  = pk2(b00 * 0.125f, b01 * 0.125f);
        s_lin2[pr] = pk2(lin0, lin1);
    }
    if (t >= 120 && t < 120 + 136) {    // info table (global const -> shared)
        int k = t - 120;
        int v = UPPER_TAB[k];
        int i = v >> 3, jb = (v & 7) * 4;
        int mask = 0;
        #pragma unroll
        for (int p = 0; p < 4; ++p) if (jb + p > i) mask |= 1 << p;
        int same = ((i < 16) == (jb < 16)) ? 1 : 0;
        s_info[k] = v | (mask << 8) | (same << 12);
    }

    // alpha coefficients straight into registers
    u64 a2[NU];
    #pragma unroll
    for (int q = 0; q < NU; ++q) { float a = alpha[q]; a2[q] = pk2(a, a); }

    __syncthreads();

    // ---- interleaved walker assignment: every SM gets a balanced share ----
    const int w = blockIdx.x + gridDim.x * warp;
    if (w >= B) return;                 // idle warps exit (no more block syncs)

    // ---- issue all 6-7 loads for this walker ----
    const float4* nrow = nuc4 + (size_t)w * 64;
    float4 n0 = __ldg(nrow + lane);
    float4 n1 = __ldg(nrow + 32 + lane);

    const float4* erow = elec4 + (size_t)w * 256;
    const int i0 = s_info[lane];
    const int i1 = s_info[lane + 32];
    const int i2 = s_info[lane + 64];
    const int i3 = s_info[lane + 96];
    float4 e0 = __ldg(erow + (i0 & 255));
    float4 e1 = __ldg(erow + (i1 & 255));
    float4 e2 = __ldg(erow + (i2 & 255));
    float4 e3 = __ldg(erow + (i3 & 255));
    const bool has4 = (lane < 8);
    int i4 = 0;
    float4 e4;
    if (has4) { i4 = s_info[128 + lane]; e4 = __ldg(erow + (i4 & 255)); }

    const u64 ss2 = s_ss2, sd2 = s_sd2;
    const float Lu = s_Lu;

    u64 acc2 = pk2(0.f, 0.f);

    // ---- nuc chunks (both share lane-parity coefficient pair) ----
    {
        const int pr0 = (lane & 1) * 2;
        const int mb  = (lane & 1) * 4;
        const float L0 = s_L[mb], L1 = s_L[mb + 1], L2 = s_L[mb + 2], L3 = s_L[mb + 3];
        const u64 h6a = s_hi2[pr0][6], h6b = s_hi2[pr0 + 1][6];

        auto do_nuc = [&](const float4& rn) {
            float d0 = fminf(rn.x - L0, 0.f);
            float d1 = fminf(rn.y - L1, 0.f);
            float d2 = fminf(rn.z - L2, 0.f);
            float d3 = fminf(rn.w - L3, 0.f);
            u64 rA = pk2(rn.x, rn.y), rB = pk2(rn.z, rn.w);
            u64 dA = pk2(d0, d1),     dB = pk2(d2, d3);
            u64 envA = mul2(mul2(dA, dA), dA);
            u64 envB = mul2(mul2(dB, dB), dB);
            u64 pA = h6a, pB = h6b;
            #pragma unroll
            for (int q = 5; q >= 0; --q) {
                pA = fma2(pA, rA, s_hi2[pr0][q]);
                pB = fma2(pB, rB, s_hi2[pr0 + 1][q]);
            }
            u64 rA2 = mul2(rA, rA), rB2 = mul2(rB, rB);
            pA = fma2(pA, rA2, fma2(s_lin2[pr0],     rA, s_c02[pr0]));
            pB = fma2(pB, rB2, fma2(s_lin2[pr0 + 1], rB, s_c02[pr0 + 1]));
            acc2 = fma2(envA, pA, acc2);
            acc2 = fma2(envB, pB, acc2);
        };
        do_nuc(n0);
        do_nuc(n1);
    }

    // ---- elec chunks: pure-register Horner ----
    auto do_chunk = [&](int info, const float4& v) {
        int mask = (info >> 8) & 15;
        u64 slope2 = (info & 0x1000) ? ss2 : sd2;
        float d0 = (mask & 1) ? fminf(v.x - Lu, 0.f) : 0.f;
        float d1 = (mask & 2) ? fminf(v.y - Lu, 0.f) : 0.f;
        float d2 = (mask & 4) ? fminf(v.z - Lu, 0.f) : 0.f;
        float d3 = (mask & 8) ? fminf(v.w - Lu, 0.f) : 0.f;
        u64 rA = pk2(v.x, v.y), rB = pk2(v.z, v.w);
        u64 dA = pk2(d0, d1),   dB = pk2(d2, d3);
        u64 envA = mul2(mul2(dA, dA), dA);
        u64 envB = mul2(mul2(dB, dB), dB);
        u64 pA = a2[NU - 1];
        u64 pB = a2[NU - 1];
        #pragma unroll
        for (int q = NU - 2; q >= 1; --q) {
            pA = fma2(pA, rA, a2[q]);
            pB = fma2(pB, rB, a2[q]);
        }
        u64 rA2 = mul2(rA, rA), rB2 = mul2(rB, rB);
        pA = fma2(pA, rA2, fma2(slope2, rA, a2[0]));
        pB = fma2(pB, rB2, fma2(slope2, rB, a2[0]));
        acc2 = fma2(envA, pA, acc2);
        acc2 = fma2(envB, pB, acc2);
    };

    do_chunk(i0, e0);
    do_chunk(i1, e1);
    do_chunk(i2, e2);
    do_chunk(i3, e3);
    if (has4) do_chunk(i4, e4);

    // ---- single-warp reduce, lane 0 writes ----
    float aLo, aHi;
    upk2(acc2, aLo, aHi);
    float acc = aLo + aHi;
    #pragma unroll
    for (int off = 16; off > 0; off >>= 1)
        acc += __shfl_down_sync(0xffffffffu, acc, off);
    if (lane == 0) out[w] = acc;
}

extern "C" void kernel_launch(void* const* d_in, const int* in_sizes, int n_in,
                              void* d_out, int out_size)
{
    const float4* elec  = (const float4*)d_in[0];
    const float4* nuc   = (const float4*)d_in[1];
    const float* alpha  = (const float*)d_in[2];
    const float* beta   = (const float*)d_in[3];
    const float* Z      = (const float*)d_in[4];
    const float* Lchi   = (const float*)d_in[5];
    const float* Lu     = (const float*)d_in[6];
    const int*   tidx   = (const int*)  d_in[7];
    float* out = (float*)d_out;

    int B = in_sizes[1] / (NE * NNUC);   // 4096

    // 296 = 2 blocks/SM x 148 SMs: one full resident wave, walker ids
    // interleaved so every SM gets a near-equal share of the 4096 walkers.
    jastrow_kernel<<<296, 512>>>(elec, nuc, alpha, beta, Z, Lchi, Lu, tidx, out, B);
}